// round 2
// baseline (speedup 1.0000x reference)
#include <cuda_runtime.h>
#include <math_constants.h>

// Problem constants
#define B_   4
#define C_   256
#define C8_  32
#define N_   4096

// Scratch (static device globals — no runtime allocation)
// g_Q: FA "keys"    = Wq@x + bq, layout [b][j][n]
// g_K: FA "queries" = Wk@x + bk, layout [b][j][m]
// g_V: values       = Wv@x + bv, layout [b][c][n]
__device__ float g_Q[B_ * C8_ * N_];
__device__ float g_K[B_ * C8_ * N_];
__device__ float g_V[B_ * C_ * N_];

// ---------------------------------------------------------------------------
// Projection: out[b][j][n] = sum_c W[j][c] * x[b][c][n] + bias[j],  j in [0,32)
// Block tile: 32 j x 128 n. 256 threads, each computes 4j x 4n.
// which = 0 -> g_Q, which = 1 -> g_K
// ---------------------------------------------------------------------------
__global__ __launch_bounds__(256) void proj32_kernel(
    const float* __restrict__ x, const float* __restrict__ W,
    const float* __restrict__ bias, int which)
{
    float* __restrict__ out = which ? g_K : g_Q;
    const int b  = blockIdx.y;
    const int n0 = blockIdx.x * 128;
    __shared__ float Xs[32][132];   // [c][n], pad to 132 for bank spread
    __shared__ float Ws[32][33];    // [j][c]
    const int tid = threadIdx.x;
    const int nl  = tid & 31;       // n lane
    const int jg  = tid >> 5;       // j group (0..7)

    float acc[4][4];
#pragma unroll
    for (int i = 0; i < 4; i++)
#pragma unroll
        for (int k = 0; k < 4; k++) acc[i][k] = 0.f;

    for (int c0 = 0; c0 < C_; c0 += 32) {
        for (int idx = tid; idx < 32 * 128; idx += 256) {
            int cc = idx >> 7, nn = idx & 127;
            Xs[cc][nn] = x[(((b << 8) + c0 + cc) << 12) + n0 + nn];
        }
        for (int idx = tid; idx < 1024; idx += 256) {
            int jj = idx >> 5, cc = idx & 31;
            Ws[jj][cc] = W[(jj << 8) + c0 + cc];
        }
        __syncthreads();
#pragma unroll
        for (int cc = 0; cc < 32; cc++) {
            float wv[4], xv[4];
#pragma unroll
            for (int ji = 0; ji < 4; ji++) wv[ji] = Ws[jg + 8 * ji][cc];
#pragma unroll
            for (int ni = 0; ni < 4; ni++) xv[ni] = Xs[cc][nl + 32 * ni];
#pragma unroll
            for (int ji = 0; ji < 4; ji++)
#pragma unroll
                for (int ni = 0; ni < 4; ni++) acc[ji][ni] += wv[ji] * xv[ni];
        }
        __syncthreads();
    }
#pragma unroll
    for (int ji = 0; ji < 4; ji++) {
        int j = jg + 8 * ji;
        float bj = bias[j];
#pragma unroll
        for (int ni = 0; ni < 4; ni++) {
            out[(((b << 5) + j) << 12) + n0 + nl + 32 * ni] = acc[ji][ni] + bj;
        }
    }
}

// ---------------------------------------------------------------------------
// V projection: out[b][c][n] = sum_p Wv[c][p] * x[b][p][n] + bv[c]
// Block tile: 64 c x 64 n. 256 threads (16x16), each computes 4c x 4n.
// ---------------------------------------------------------------------------
__global__ __launch_bounds__(256) void projv_kernel(
    const float* __restrict__ x, const float* __restrict__ W,
    const float* __restrict__ bias)
{
    const int b  = blockIdx.z;
    const int c0 = blockIdx.y * 64;
    const int n0 = blockIdx.x * 64;
    __shared__ float Xs[64][68];    // [p][n]
    __shared__ float WsT[64][68];   // [p][c]
    const int tid = threadIdx.x;
    const int tx = tid & 15;        // n quad: n = n0 + tx*4 + {0..3}
    const int ty = tid >> 4;        // c quad: c = c0 + ty*4 + {0..3}

    float acc[4][4];
#pragma unroll
    for (int i = 0; i < 4; i++)
#pragma unroll
        for (int k = 0; k < 4; k++) acc[i][k] = 0.f;

    for (int p0 = 0; p0 < C_; p0 += 64) {
        for (int idx = tid; idx < 4096; idx += 256) {
            int pp = idx >> 6, nn = idx & 63;
            Xs[pp][nn] = x[(((b << 8) + p0 + pp) << 12) + n0 + nn];
        }
        for (int idx = tid; idx < 4096; idx += 256) {
            int cc = idx >> 6, pp = idx & 63;
            WsT[pp][cc] = W[((c0 + cc) << 8) + p0 + pp];
        }
        __syncthreads();
#pragma unroll
        for (int pp = 0; pp < 64; pp++) {
            const float4 a  = *(const float4*)&WsT[pp][ty * 4];
            const float4 xb = *(const float4*)&Xs[pp][tx * 4];
            acc[0][0] += a.x * xb.x; acc[0][1] += a.x * xb.y;
            acc[0][2] += a.x * xb.z; acc[0][3] += a.x * xb.w;
            acc[1][0] += a.y * xb.x; acc[1][1] += a.y * xb.y;
            acc[1][2] += a.y * xb.z; acc[1][3] += a.y * xb.w;
            acc[2][0] += a.z * xb.x; acc[2][1] += a.z * xb.y;
            acc[2][2] += a.z * xb.z; acc[2][3] += a.z * xb.w;
            acc[3][0] += a.w * xb.x; acc[3][1] += a.w * xb.y;
            acc[3][2] += a.w * xb.z; acc[3][3] += a.w * xb.w;
        }
        __syncthreads();
    }
#pragma unroll
    for (int i = 0; i < 4; i++) {
        int c = c0 + ty * 4 + i;
        float bc = bias[c];
        float4 r = make_float4(acc[i][0] + bc, acc[i][1] + bc,
                               acc[i][2] + bc, acc[i][3] + bc);
        *(float4*)&g_V[(((size_t)(b << 8) + c) << 12) + n0 + tx * 4] = r;
    }
}

// ---------------------------------------------------------------------------
// Flash attention (softmax over n, per output column m):
//   S[n,m] = sum_j g_Q[b][j][n] * g_K[b][j][m]
//   A = softmax_n(S);  out[c][m] = gamma * sum_n g_V[c][n] A[n,m] / l + x[c][m]
// Block: 32 m positions, 256 threads. Thread (ml = tid/8, g = tid%8) owns
// query m0+ml and channels c = g + 8k, k in [0,32).
// ---------------------------------------------------------------------------
__global__ __launch_bounds__(256) void attn_kernel(
    const float* __restrict__ xin, const float* __restrict__ gamma,
    float* __restrict__ out)
{
    const int b     = blockIdx.y;
    const int m0    = blockIdx.x << 5;
    const int tid   = threadIdx.x;
    const int g     = tid & 7;
    const int ml    = tid >> 3;
    const int mglob = m0 + ml;

    __shared__ float Ks[32][33];    // key tile     [n][j]
    __shared__ float Vs[256][36];   // value tile   [c][n]  (stride 36: 16B-aligned, conflict-free)
    __shared__ float Ps[32][36];    // probs        [m][n]

    // query vector (d=32) in registers
    float q[32];
    const float* kbase = g_K + ((size_t)b << 17) + mglob;
#pragma unroll
    for (int j = 0; j < 32; j++) q[j] = __ldg(&kbase[(size_t)j << 12]);

    float acc[32];
#pragma unroll
    for (int k = 0; k < 32; k++) acc[k] = 0.f;
    float run_max = -CUDART_INF_F;
    float l = 0.f;

    for (int n0 = 0; n0 < N_; n0 += 32) {
        // stage key tile [32 n][32 j]
        for (int idx = tid; idx < 1024; idx += 256) {
            int j = idx >> 5, nn = idx & 31;
            Ks[nn][j] = g_Q[((size_t)b << 17) + ((size_t)j << 12) + n0 + nn];
        }
        // stage value tile [256 c][32 n]
        for (int idx = tid; idx < 8192; idx += 256) {
            int c = idx >> 5, nn = idx & 31;
            Vs[c][nn] = g_V[(((size_t)(b << 8) + c) << 12) + n0 + nn];
        }
        __syncthreads();

        // S: this thread computes 4 scores (n = g + 8i)
        float s[4];
#pragma unroll
        for (int i = 0; i < 4; i++) {
            const int nn = g + (i << 3);
            float a0 = 0.f;
#pragma unroll
            for (int j = 0; j < 32; j++) a0 += q[j] * Ks[nn][j];
            s[i] = a0;
        }

        // online softmax over the 8-lane group owning row ml
        float tmax = fmaxf(fmaxf(s[0], s[1]), fmaxf(s[2], s[3]));
        tmax = fmaxf(tmax, __shfl_xor_sync(0xffffffffu, tmax, 1));
        tmax = fmaxf(tmax, __shfl_xor_sync(0xffffffffu, tmax, 2));
        tmax = fmaxf(tmax, __shfl_xor_sync(0xffffffffu, tmax, 4));
        const float nmax = fmaxf(run_max, tmax);
        const float corr = __expf(run_max - nmax);
        float psum = 0.f;
#pragma unroll
        for (int i = 0; i < 4; i++) {
            float p = __expf(s[i] - nmax);
            psum += p;
            Ps[ml][g + (i << 3)] = p;
        }
        psum += __shfl_xor_sync(0xffffffffu, psum, 1);
        psum += __shfl_xor_sync(0xffffffffu, psum, 2);
        psum += __shfl_xor_sync(0xffffffffu, psum, 4);
        l = l * corr + psum;
        run_max = nmax;
#pragma unroll
        for (int k = 0; k < 32; k++) acc[k] *= corr;
        __syncwarp();

        // PV: acc[k] += sum_n Ps[ml][n] * Vs[g+8k][n]
#pragma unroll
        for (int nq = 0; nq < 8; nq++) {
            const float4 p4 = *(const float4*)&Ps[ml][nq << 2];
#pragma unroll
            for (int k = 0; k < 32; k++) {
                const float4 v4 = *(const float4*)&Vs[g + (k << 3)][nq << 2];
                acc[k] += p4.x * v4.x + p4.y * v4.y + p4.z * v4.z + p4.w * v4.w;
            }
        }
        __syncthreads();
    }

    const float gam   = *gamma;
    const float inv_l = 1.0f / l;
#pragma unroll
    for (int k = 0; k < 32; k++) {
        const int c = g + (k << 3);
        const size_t idx = (((size_t)(b << 8) + c) << 12) + mglob;
        out[idx] = gam * acc[k] * inv_l + xin[idx];
    }
}

// ---------------------------------------------------------------------------
extern "C" void kernel_launch(void* const* d_in, const int* in_sizes, int n_in,
                              void* d_out, int out_size)
{
    const float* x     = (const float*)d_in[0];
    const float* Wq    = (const float*)d_in[1];
    const float* bq    = (const float*)d_in[2];
    const float* Wk    = (const float*)d_in[3];
    const float* bk    = (const float*)d_in[4];
    const float* Wv    = (const float*)d_in[5];
    const float* bv    = (const float*)d_in[6];
    const float* gamma = (const float*)d_in[7];
    float* out = (float*)d_out;

    // Projections into device-global scratch
    proj32_kernel<<<dim3(N_ / 128, B_), 256>>>(x, Wq, bq, /*which=*/0); // g_Q (FA keys)
    proj32_kernel<<<dim3(N_ / 128, B_), 256>>>(x, Wk, bk, /*which=*/1); // g_K (FA queries)
    projv_kernel<<<dim3(N_ / 64, C_ / 64, B_), 256>>>(x, Wv, bv);       // g_V

    // Flash attention + residual epilogue
    attn_kernel<<<dim3(N_ / 32, B_), 256>>>(x, gamma, out);
}